// round 12
// baseline (speedup 1.0000x reference)
#include <cuda_runtime.h>
#include <cuda_bf16.h>
#include <cuda_fp16.h>
#include <stdint.h>

#define BQ   32
#define SEQ  1024
#define DIM  512
#define NTOK (BQ*SEQ)
typedef __nv_bfloat16 bf16;

// ---------------- scratch (device globals; no allocs allowed) ----------------
__device__ bf16 g_xh[NTOK*DIM], g_xl[NTOK*DIM];
__device__ __half g_xf[NTOK*DIM];                 // x as fp16 single (V path)
__device__ bf16 g_qh[NTOK*DIM], g_ql[NTOK*DIM];
__device__ bf16 g_kh[NTOK*DIM], g_kl[NTOK*DIM];
__device__ __half g_vf[NTOK*DIM];                 // V as fp16 single
__device__ __half g_af[(size_t)BQ*SEQ*SEQ];       // attn weights, fp16 single
__device__ float g_s[(size_t)BQ*SEQ*SEQ];
__device__ bf16 g_wh[3*DIM*DIM], g_wl[3*DIM*DIM]; // slots q,k bf16; slot v fp16 bits

__device__ __forceinline__ void split2(float x, bf16& h, bf16& l)
{
    h = __float2bfloat16(x);
    l = __float2bfloat16(x - __bfloat162float(h));
}
__device__ __forceinline__ void split2h(float x, __half& h, __half& l)
{
    h = __float2half_rn(x);
    l = __float2half_rn(x - __half2float(h));
}

// ---------------- PTX helpers ----------------
__device__ __forceinline__ uint32_t smem_u32(const void* p){
    return (uint32_t)__cvta_generic_to_shared(p);
}
__device__ __forceinline__ void cp16(uint32_t s, const void* g){
    asm volatile("cp.async.cg.shared.global [%0],[%1],16;\n" :: "r"(s), "l"(g));
}
__device__ __forceinline__ void cp_commit(){ asm volatile("cp.async.commit_group;\n" ::: "memory"); }
template<int N> __device__ __forceinline__ void cp_wait(){
    asm volatile("cp.async.wait_group %0;\n" :: "n"(N) : "memory");
}
__device__ __forceinline__ void ldsm4(uint32_t* r, uint32_t a){
    asm volatile("ldmatrix.sync.aligned.m8n8.x4.shared.b16 {%0,%1,%2,%3},[%4];\n"
        : "=r"(r[0]),"=r"(r[1]),"=r"(r[2]),"=r"(r[3]) : "r"(a));
}
__device__ __forceinline__ void ldsm4t(uint32_t* r, uint32_t a){
    asm volatile("ldmatrix.sync.aligned.m8n8.x4.trans.shared.b16 {%0,%1,%2,%3},[%4];\n"
        : "=r"(r[0]),"=r"(r[1]),"=r"(r[2]),"=r"(r[3]) : "r"(a));
}
__device__ __forceinline__ void mma16816(float* d, const uint32_t* a, const uint32_t* b)
{
    asm volatile(
        "mma.sync.aligned.m16n8k16.row.col.f32.bf16.bf16.f32 "
        "{%0,%1,%2,%3},{%4,%5,%6,%7},{%8,%9},{%0,%1,%2,%3};\n"
        : "+f"(d[0]), "+f"(d[1]), "+f"(d[2]), "+f"(d[3])
        : "r"(a[0]), "r"(a[1]), "r"(a[2]), "r"(a[3]), "r"(b[0]), "r"(b[1]));
}
__device__ __forceinline__ void mma16816h(float* d, const uint32_t* a, const uint32_t* b)
{
    asm volatile(
        "mma.sync.aligned.m16n8k16.row.col.f32.f16.f16.f32 "
        "{%0,%1,%2,%3},{%4,%5,%6,%7},{%8,%9},{%0,%1,%2,%3};\n"
        : "+f"(d[0]), "+f"(d[1]), "+f"(d[2]), "+f"(d[3])
        : "r"(a[0]), "r"(a[1]), "r"(a[2]), "r"(a[3]), "r"(b[0]), "r"(b[1]));
}

// K-major tile swizzle: 128 rows x 32 elems (64B/row). Conflict-free for
// cp.async writes and ldmatrix reads.
__device__ __forceinline__ uint32_t swzA(int r, int kcol)
{
    const int line = r >> 1;
    const int cc = ((r & 1) << 2) | (kcol >> 3);
    return (uint32_t)(line * 128 + ((cc ^ (line & 7)) << 4));
}

// ---------------- kernel: embedding+LN (blocks < NTOK) + weight split (rest) --
__global__ void embed_ln_split_kernel(const int* __restrict__ inp,
                                      const float* __restrict__ wemb,
                                      const float* __restrict__ pemb,
                                      const float* __restrict__ gamma,
                                      const float* __restrict__ beta,
                                      const float* __restrict__ wq,
                                      const float* __restrict__ wk,
                                      const float* __restrict__ wv)
{
    const int b = blockIdx.x;
    const int tid = threadIdx.x;                     // 0..127

    if (b >= NTOK) {
        // ---- weight split: 512 elems per block ----
        const int i0 = (b - NTOK) * 512 + tid * 4;
        #pragma unroll
        for (int j = 0; j < 4; j++) {
            const int i = i0 + j;
            const int slot = i / (DIM*DIM);
            const int off  = i - slot * (DIM*DIM);
            if (slot == 2) {
                __half h, l;
                split2h(wv[off], h, l);
                ((__half*)g_wh)[i] = h; ((__half*)g_wl)[i] = l;
            } else {
                const float* src = (slot == 0) ? wq : wk;
                bf16 h, l;
                split2(src[off], h, l);
                g_wh[i] = h; g_wl[i] = l;
            }
        }
        return;
    }

    const int tok = b;
    const int s   = tok & (SEQ - 1);
    const int id  = inp[tok];

    const float4 w = ((const float4*)(wemb + (long long)id * DIM))[tid];
    const float4 p = ((const float4*)(pemb + (long long)s  * DIM))[tid];
    float4 e;
    e.x = w.x + p.x; e.y = w.y + p.y; e.z = w.z + p.z; e.w = w.w + p.w;

    float sum = e.x + e.y + e.z + e.w;
    float sq  = e.x*e.x + e.y*e.y + e.z*e.z + e.w*e.w;

    __shared__ float sS[4], sQ[4];
    #pragma unroll
    for (int o = 16; o > 0; o >>= 1) {
        sum += __shfl_xor_sync(0xFFFFFFFFu, sum, o);
        sq  += __shfl_xor_sync(0xFFFFFFFFu, sq,  o);
    }
    if ((tid & 31) == 0) { sS[tid >> 5] = sum; sQ[tid >> 5] = sq; }
    __syncthreads();
    sum = sS[0] + sS[1] + sS[2] + sS[3];
    sq  = sQ[0] + sQ[1] + sQ[2] + sQ[3];

    const float mean = sum * (1.0f / DIM);
    const float var  = sq  * (1.0f / DIM) - mean * mean;
    const float inv  = rsqrtf(var + 1e-5f);

    const float4 ga = ((const float4*)gamma)[tid];
    const float4 be = ((const float4*)beta)[tid];
    float o0 = (e.x - mean) * inv * ga.x + be.x;
    float o1 = (e.y - mean) * inv * ga.y + be.y;
    float o2 = (e.z - mean) * inv * ga.z + be.z;
    float o3 = (e.w - mean) * inv * ga.w + be.w;

    bf16 h0,h1,h2,h3,l0,l1,l2,l3;
    split2(o0,h0,l0); split2(o1,h1,l1); split2(o2,h2,l2); split2(o3,h3,l3);
    const long long base = (long long)tok * DIM + tid * 4;
    *(__nv_bfloat162*)&g_xh[base]   = __nv_bfloat162(h0,h1);
    *(__nv_bfloat162*)&g_xh[base+2] = __nv_bfloat162(h2,h3);
    *(__nv_bfloat162*)&g_xl[base]   = __nv_bfloat162(l0,l1);
    *(__nv_bfloat162*)&g_xl[base+2] = __nv_bfloat162(l2,l3);
    *(__half2*)&g_xf[base]   = __half2(__float2half_rn(o0), __float2half_rn(o1));
    *(__half2*)&g_xf[base+2] = __half2(__float2half_rn(o2), __float2half_rn(o3));
}

// ---------------------------------------------------------------------------
// GEMM body (device fn): C[M,N] = A[M,K] * B.
//   BKN=0 : B global [N][K] -> ldmatrix; BKN=1 : B global [K][N] -> ldmatrix.trans
//   OSPLIT: 0 = fp32 C; 1 = bf16 hi/lo C; 2 = fp16 single C (-> g_vf)
//   PROJ: 0 = generic batched; 1 = Q/K projection; 2 = V projection
//   AVM : 0 = bf16 3-pass; 1 = f16 2-pass; 2 = f16 1-pass
// QK instance (OSPLIT==0 && BKN==0) scales C by 1/sqrt(512) at store.
// 128x128x32 tiles, 256 thr, 3-stage cp.async (loads issued BEFORE compute).
// ---------------------------------------------------------------------------
template<int BKN, int OSPLIT, int PROJ, int AVM>
__device__ __forceinline__ void
gemm_body(const bf16* __restrict__ Ah_g, const bf16* __restrict__ Al_g,
          const bf16* __restrict__ Bh_g, const bf16* __restrict__ Bl_g,
          float* __restrict__ Cf, bf16* __restrict__ Ch_p, bf16* __restrict__ Cl_p,
          int K, int lda, int ldb, int ldc,
          long long sA, long long sB, long long sC, int z, char* smem)
{
    constexpr int S = 3;
    constexpr int MATSZ = 8192;
    constexpr int STAGE = 4 * MATSZ;        // 32KB

    const uint32_t sbase = smem_u32(smem);

    const int tid  = threadIdx.x;
    const int warp = tid >> 5, lane = tid & 31;

    const bf16 *Ah, *Al, *Bh, *Bl;
    bf16 *Ch, *Cl;
    if (PROJ == 1) {
        Ah = Ah_g + (long long)blockIdx.y * 128 * lda;
        Al = Al_g + (long long)blockIdx.y * 128 * lda;
        Bh = g_wh + z * (DIM*DIM) + blockIdx.x * 128;
        Bl = g_wl + z * (DIM*DIM) + blockIdx.x * 128;
        Ch = (z == 0) ? g_qh : g_kh;
        Cl = (z == 0) ? g_ql : g_kl;
    } else if (PROJ == 2) {
        Ah = (const bf16*)g_xf + (long long)blockIdx.y * 128 * lda;
        Al = nullptr;
        Bh = g_wh + 2 * (DIM*DIM) + blockIdx.x * 128;   // fp16 bits
        Bl = g_wl + 2 * (DIM*DIM) + blockIdx.x * 128;
        Ch = nullptr; Cl = nullptr;
    } else {
        Ah = Ah_g + z * sA + (long long)blockIdx.y * 128 * lda;
        Al = (AVM == 0) ? (Al_g + z * sA + (long long)blockIdx.y * 128 * lda) : nullptr;
        if (BKN == 0) { Bh = Bh_g + z*sB + (long long)blockIdx.x * 128 * ldb;
                        Bl = Bl_g + z*sB + (long long)blockIdx.x * 128 * ldb; }
        else          { Bh = Bh_g + z*sB + blockIdx.x * 128;
                        Bl = (AVM == 2) ? nullptr : (Bl_g + z*sB + blockIdx.x * 128); }
        Ch = Ch_p; Cl = Cl_p;
    }

    const int wm = (warp >> 2) * 64;
    const int wn = (warp & 3) * 32;

    float acc[4][4][4];
    #pragma unroll
    for (int i = 0; i < 4; i++)
        #pragma unroll
        for (int j = 0; j < 4; j++)
            #pragma unroll
            for (int c = 0; c < 4; c++) acc[i][j][c] = 0.0f;

    auto load_tile = [&](int s, int kt) {
        const uint32_t aOff  = sbase + s * STAGE;
        const uint32_t alOff = aOff + MATSZ;
        const uint32_t bOff  = aOff + 2*MATSZ;
        const uint32_t blOff = bOff + MATSZ;
        {
            const int r  = tid >> 1;
            const int cb = (tid & 1) * 2;
            #pragma unroll
            for (int j = 0; j < 2; j++) {
                const int c = cb + j;
                const long long go = (long long)r * lda + kt + c * 8;
                const uint32_t so = swzA(r, c * 8);
                cp16(aOff  + so, Ah + go);
                if (AVM == 0) cp16(alOff + so, Al + go);
            }
        }
        if (BKN == 0) {
            const int r  = tid >> 1;
            const int cb = (tid & 1) * 2;
            #pragma unroll
            for (int j = 0; j < 2; j++) {
                const int c = cb + j;
                const long long go = (long long)r * ldb + kt + c * 8;
                const uint32_t so = swzA(r, c * 8);
                cp16(bOff  + so, Bh + go);
                cp16(blOff + so, Bl + go);
            }
        } else {
            const int k  = tid >> 3;
            const int cb = (tid & 7) * 2;
            #pragma unroll
            for (int j = 0; j < 2; j++) {
                const int c = cb + j;
                const long long go = (long long)(kt + k) * ldb + c * 8;
                const uint32_t so = (uint32_t)(k * 256 + ((c ^ (k & 7)) * 16));
                cp16(bOff  + so, Bh + go);
                if (AVM != 2) cp16(blOff + so, Bl + go);
            }
        }
    };

    auto compute_tile = [&](int s) {
        const uint32_t aB  = sbase + s * STAGE;
        const uint32_t alB = aB + MATSZ;
        const uint32_t bB  = aB + 2*MATSZ;
        const uint32_t blB = bB + MATSZ;
        const int g = lane >> 3, idx = lane & 7;
        #pragma unroll
        for (int ks = 0; ks < 2; ks++) {
            const int k0 = ks * 16;
            uint32_t aH[4][4], aL[4][4], bH[4][2], bL[4][2];
            {
                const int arow = wm + (g & 1) * 8 + idx;
                const int acol = k0 + (g >> 1) * 8;
                #pragma unroll
                for (int mt = 0; mt < 4; mt++) {
                    const uint32_t so = swzA(arow + mt*16, acol);
                    ldsm4(aH[mt], aB  + so);
                    if (AVM == 0) ldsm4(aL[mt], alB + so);
                }
            }
            if (BKN == 0) {
                const int brow = wn + (g >> 1) * 8 + idx;
                const int bcol = k0 + (g & 1) * 8;
                #pragma unroll
                for (int p = 0; p < 2; p++) {
                    const uint32_t so = swzA(brow + p*16, bcol);
                    uint32_t r[4];
                    ldsm4(r, bB + so);
                    bH[2*p][0]=r[0]; bH[2*p][1]=r[1]; bH[2*p+1][0]=r[2]; bH[2*p+1][1]=r[3];
                    ldsm4(r, blB + so);
                    bL[2*p][0]=r[0]; bL[2*p][1]=r[1]; bL[2*p+1][0]=r[2]; bL[2*p+1][1]=r[3];
                }
            } else {
                const int krow = k0 + (g & 1) * 8 + idx;
                #pragma unroll
                for (int p = 0; p < 2; p++) {
                    const int nch = (wn + p*16 + (g >> 1) * 8) >> 3;
                    const uint32_t so = (uint32_t)(krow * 256 + ((nch ^ (krow & 7)) * 16));
                    uint32_t r[4];
                    ldsm4t(r, bB + so);
                    bH[2*p][0]=r[0]; bH[2*p][1]=r[1]; bH[2*p+1][0]=r[2]; bH[2*p+1][1]=r[3];
                    if (AVM != 2) {
                        ldsm4t(r, blB + so);
                        bL[2*p][0]=r[0]; bL[2*p][1]=r[1]; bL[2*p+1][0]=r[2]; bL[2*p+1][1]=r[3];
                    }
                }
            }
            if (AVM == 0) {
                #pragma unroll
                for (int mt = 0; mt < 4; mt++)
                    #pragma unroll
                    for (int nt = 0; nt < 4; nt++) mma16816(acc[mt][nt], aH[mt], bH[nt]);
                #pragma unroll
                for (int mt = 0; mt < 4; mt++)
                    #pragma unroll
                    for (int nt = 0; nt < 4; nt++) mma16816(acc[mt][nt], aL[mt], bH[nt]);
                #pragma unroll
                for (int mt = 0; mt < 4; mt++)
                    #pragma unroll
                    for (int nt = 0; nt < 4; nt++) mma16816(acc[mt][nt], aH[mt], bL[nt]);
            } else if (AVM == 1) {
                #pragma unroll
                for (int mt = 0; mt < 4; mt++)
                    #pragma unroll
                    for (int nt = 0; nt < 4; nt++) mma16816h(acc[mt][nt], aH[mt], bH[nt]);
                #pragma unroll
                for (int mt = 0; mt < 4; mt++)
                    #pragma unroll
                    for (int nt = 0; nt < 4; nt++) mma16816h(acc[mt][nt], aH[mt], bL[nt]);
            } else {
                #pragma unroll
                for (int mt = 0; mt < 4; mt++)
                    #pragma unroll
                    for (int nt = 0; nt < 4; nt++) mma16816h(acc[mt][nt], aH[mt], bH[nt]);
            }
        }
    };

    const int T = K / 32;
    #pragma unroll
    for (int s = 0; s < S - 1; s++) { load_tile(s, s * 32); cp_commit(); }

    for (int t = 0; t < T; t++) {
        cp_wait<S - 2>();
        __syncthreads();
        const int tn = t + S - 1;
        if (tn < T) load_tile(tn % S, tn * 32);
        cp_commit();
        compute_tile(t % S);
    }

    const int r  = lane >> 2;
    const int c2 = (lane & 3) * 2;
    if (OSPLIT == 0) {
        // QK instance folds the softmax scale into the store
        const float cs = (BKN == 0) ? 0.044194173824159216f : 1.0f;
        float* C = Cf + z * sC + (long long)blockIdx.y * 128 * ldc + blockIdx.x * 128;
        #pragma unroll
        for (int mt = 0; mt < 4; mt++)
            #pragma unroll
            for (int nt = 0; nt < 4; nt++) {
                const long long row = wm + mt * 16 + r;
                const int col = wn + nt * 8 + c2;
                *(float2*)&C[row * ldc + col]       = make_float2(acc[mt][nt][0]*cs, acc[mt][nt][1]*cs);
                *(float2*)&C[(row + 8) * ldc + col] = make_float2(acc[mt][nt][2]*cs, acc[mt][nt][3]*cs);
            }
    } else if (OSPLIT == 2) {
        __half* CH = g_vf + (long long)blockIdx.y * 128 * ldc + blockIdx.x * 128;
        #pragma unroll
        for (int mt = 0; mt < 4; mt++)
            #pragma unroll
            for (int nt = 0; nt < 4; nt++) {
                const long long row = wm + mt * 16 + r;
                const int col = wn + nt * 8 + c2;
                *(__half2*)&CH[row * ldc + col] =
                    __half2(__float2half_rn(acc[mt][nt][0]), __float2half_rn(acc[mt][nt][1]));
                *(__half2*)&CH[(row+8) * ldc + col] =
                    __half2(__float2half_rn(acc[mt][nt][2]), __float2half_rn(acc[mt][nt][3]));
            }
    } else {
        bf16* CH = Ch + (long long)blockIdx.y * 128 * ldc + blockIdx.x * 128;
        bf16* CL = Cl + (long long)blockIdx.y * 128 * ldc + blockIdx.x * 128;
        if (PROJ == 0) { CH += z * sC; CL += z * sC; }
        #pragma unroll
        for (int mt = 0; mt < 4; mt++)
            #pragma unroll
            for (int nt = 0; nt < 4; nt++) {
                const long long row = wm + mt * 16 + r;
                const int col = wn + nt * 8 + c2;
                bf16 h0,h1,l0,l1;
                split2(acc[mt][nt][0], h0, l0); split2(acc[mt][nt][1], h1, l1);
                *(__nv_bfloat162*)&CH[row * ldc + col] = __nv_bfloat162(h0,h1);
                *(__nv_bfloat162*)&CL[row * ldc + col] = __nv_bfloat162(l0,l1);
                split2(acc[mt][nt][2], h0, l0); split2(acc[mt][nt][3], h1, l1);
                *(__nv_bfloat162*)&CH[(row+8) * ldc + col] = __nv_bfloat162(h0,h1);
                *(__nv_bfloat162*)&CL[(row+8) * ldc + col] = __nv_bfloat162(l0,l1);
            }
    }
}

// ---------------- GEMM kernels ----------------
template<int BKN, int OSPLIT, int PROJ, int AVM>
__global__ void __launch_bounds__(256, 2)
gemm2(const bf16* __restrict__ Ah_g, const bf16* __restrict__ Al_g,
      const bf16* __restrict__ Bh_g, const bf16* __restrict__ Bl_g,
      float* __restrict__ Cf, bf16* __restrict__ Ch_p, bf16* __restrict__ Cl_p,
      int K, int lda, int ldb, int ldc,
      long long sA, long long sB, long long sC)
{
    extern __shared__ char smem[];
    gemm_body<BKN,OSPLIT,PROJ,AVM>(Ah_g, Al_g, Bh_g, Bl_g, Cf, Ch_p, Cl_p,
                                   K, lda, ldb, ldc, sA, sB, sC, blockIdx.z, smem);
}

// merged tri-projection: z 0,1 = Q/K (bf16 3-pass); z 2 = V (fp16 2-pass)
__global__ void __launch_bounds__(256, 2)
proj_all_kernel(const bf16* __restrict__ xh, const bf16* __restrict__ xl)
{
    extern __shared__ char smem[];
    const int z = blockIdx.z;
    if (z < 2) {
        gemm_body<1,1,1,0>(xh, xl, nullptr, nullptr, nullptr, nullptr, nullptr,
                           DIM, DIM, DIM, DIM, 0, 0, 0, z, smem);
    } else {
        gemm_body<1,2,2,1>(nullptr, nullptr, nullptr, nullptr, nullptr, nullptr, nullptr,
                           DIM, DIM, DIM, DIM, 0, 0, 0, z, smem);
    }
}

// ---------------- kernel: softmax -> attn fp16 (reverse row order for L2) ----
// Scores are pre-scaled by QK epilogue.
__global__ void softmax_kernel(const float* __restrict__ Sc)
{
    const long long lin = (long long)blockIdx.y * SEQ + blockIdx.x;
    const long long row = (long long)BQ * SEQ - 1 - lin;   // reverse: read hottest first
    const float4* p = (const float4*)(Sc + row * SEQ);
    const int tid = threadIdx.x;
    const int warp = tid >> 5, lane = tid & 31;

    float4 v = p[tid];

    __shared__ float redM[8], redS[8];

    float mx = fmaxf(fmaxf(v.x, v.y), fmaxf(v.z, v.w));
    #pragma unroll
    for (int o = 16; o > 0; o >>= 1) mx = fmaxf(mx, __shfl_xor_sync(0xFFFFFFFFu, mx, o));
    if (lane == 0) redM[warp] = mx;
    __syncthreads();
    mx = redM[0];
    #pragma unroll
    for (int i = 1; i < 8; i++) mx = fmaxf(mx, redM[i]);

    float e0 = expf(v.x - mx), e1 = expf(v.y - mx);
    float e2 = expf(v.z - mx), e3 = expf(v.w - mx);
    float sum = e0 + e1 + e2 + e3;
    #pragma unroll
    for (int o = 16; o > 0; o >>= 1) sum += __shfl_xor_sync(0xFFFFFFFFu, sum, o);
    if (lane == 0) redS[warp] = sum;
    __syncthreads();
    sum = redS[0]+redS[1]+redS[2]+redS[3]+redS[4]+redS[5]+redS[6]+redS[7];

    const float inv = 1.0f / sum;
    const long long base = row * SEQ + tid * 4;
    *(__half2*)&g_af[base]   = __half2(__float2half_rn(e0*inv), __float2half_rn(e1*inv));
    *(__half2*)&g_af[base+2] = __half2(__float2half_rn(e2*inv), __float2half_rn(e3*inv));
}

// ---------------------------------------------------------------------------
extern "C" void kernel_launch(void* const* d_in, const int* in_sizes, int n_in,
                              void* d_out, int out_size)
{
    const int*   inp   = (const int*)  d_in[0];
    const float* wemb  = (const float*)d_in[1];
    const float* pemb  = (const float*)d_in[2];
    const float* gamma = (const float*)d_in[3];
    const float* beta  = (const float*)d_in[4];
    const float* Wk    = (const float*)d_in[5];
    const float* Wq    = (const float*)d_in[6];
    const float* Wv    = (const float*)d_in[7];
    float* out = (float*)d_out;

    bf16 *xh,*xl,*qh,*ql,*kh,*kl;
    __half *vf,*af;
    float *ps;
    cudaGetSymbolAddress((void**)&xh, g_xh); cudaGetSymbolAddress((void**)&xl, g_xl);
    cudaGetSymbolAddress((void**)&qh, g_qh); cudaGetSymbolAddress((void**)&ql, g_ql);
    cudaGetSymbolAddress((void**)&kh, g_kh); cudaGetSymbolAddress((void**)&kl, g_kl);
    cudaGetSymbolAddress((void**)&vf, g_vf);
    cudaGetSymbolAddress((void**)&af, g_af);
    cudaGetSymbolAddress((void**)&ps, g_s);

    const int SMEMSZ = 3 * 32768;  // 98304 B -> 2 CTAs/SM
    cudaFuncSetAttribute(proj_all_kernel, cudaFuncAttributeMaxDynamicSharedMemorySize, SMEMSZ);
    cudaFuncSetAttribute(gemm2<0,0,0,0>, cudaFuncAttributeMaxDynamicSharedMemorySize, SMEMSZ);
    cudaFuncSetAttribute(gemm2<1,0,0,2>, cudaFuncAttributeMaxDynamicSharedMemorySize, SMEMSZ);

    // 1) embedding + layernorm + weight split in ONE launch
    const int splitBlocks = 3 * DIM * DIM / 512;   // 1536
    embed_ln_split_kernel<<<NTOK + splitBlocks, 128>>>(inp, wemb, pemb, gamma, beta,
                                                       Wq, Wk, Wv);

    // 2) ALL projections in one launch (z: 0=Q, 1=K bf16 3-pass; 2=V fp16 2-pass)
    dim3 gproj(DIM/128, NTOK/128, 3);
    proj_all_kernel<<<gproj, 256, SMEMSZ>>>(xh, xl);

    // 3) scores = Q @ K^T (batched, bf16 x3) — scaled at store
    dim3 gsc(SEQ/128, SEQ/128, BQ);
    gemm2<0,0,0,0><<<gsc, 256, SMEMSZ>>>(qh, ql, kh, kl, ps, nullptr, nullptr,
                                         DIM, DIM, DIM, SEQ,
                                         (long long)SEQ*DIM, (long long)SEQ*DIM,
                                         (long long)SEQ*SEQ);

    // 4) softmax (reverse order, L2-hot) -> attn fp16 single
    softmax_kernel<<<dim3(SEQ, BQ), 256>>>(ps);

    // 5) out = attn(fp16) @ V(fp16 single), 1 MMA pass
    dim3 gav(DIM/128, SEQ/128, BQ);
    gemm2<1,0,0,2><<<gav, 256, SMEMSZ>>>((const bf16*)af, nullptr, (const bf16*)vf, nullptr,
                                         out, nullptr, nullptr,
                                         SEQ, SEQ, DIM, DIM,
                                         (long long)SEQ*SEQ, (long long)SEQ*DIM,
                                         (long long)SEQ*DIM);
}

// round 14
// speedup vs baseline: 1.6260x; 1.6260x over previous
#include <cuda_runtime.h>
#include <cuda_bf16.h>
#include <cuda_fp16.h>
#include <stdint.h>

#define BQ   32
#define SEQ  1024
#define DIM  512
#define NTOK (BQ*SEQ)
typedef __nv_bfloat16 bf16;

// ---------------- scratch (device globals; no allocs allowed) ----------------
__device__ bf16 g_xh[NTOK*DIM], g_xl[NTOK*DIM];
__device__ __half g_xf[NTOK*DIM];                 // x as fp16 single (V path)
__device__ bf16 g_qh[NTOK*DIM], g_ql[NTOK*DIM];
__device__ bf16 g_kh[NTOK*DIM], g_kl[NTOK*DIM];
__device__ __half g_vf[NTOK*DIM];                 // V as fp16 single
__device__ __half g_af[(size_t)BQ*SEQ*SEQ];       // attn weights, fp16 single
__device__ float g_s[(size_t)BQ*SEQ*SEQ];
__device__ bf16 g_wh[3*DIM*DIM], g_wl[3*DIM*DIM]; // slots q,k bf16; slot v fp16 bits

__device__ __forceinline__ void split2(float x, bf16& h, bf16& l)
{
    h = __float2bfloat16(x);
    l = __float2bfloat16(x - __bfloat162float(h));
}
__device__ __forceinline__ void split2h(float x, __half& h, __half& l)
{
    h = __float2half_rn(x);
    l = __float2half_rn(x - __half2float(h));
}

// ---------------- PTX helpers ----------------
__device__ __forceinline__ uint32_t smem_u32(const void* p){
    return (uint32_t)__cvta_generic_to_shared(p);
}
__device__ __forceinline__ void cp16(uint32_t s, const void* g){
    asm volatile("cp.async.cg.shared.global [%0],[%1],16;\n" :: "r"(s), "l"(g));
}
__device__ __forceinline__ void cp_commit(){ asm volatile("cp.async.commit_group;\n" ::: "memory"); }
template<int N> __device__ __forceinline__ void cp_wait(){
    asm volatile("cp.async.wait_group %0;\n" :: "n"(N) : "memory");
}
__device__ __forceinline__ void ldsm4(uint32_t* r, uint32_t a){
    asm volatile("ldmatrix.sync.aligned.m8n8.x4.shared.b16 {%0,%1,%2,%3},[%4];\n"
        : "=r"(r[0]),"=r"(r[1]),"=r"(r[2]),"=r"(r[3]) : "r"(a));
}
__device__ __forceinline__ void ldsm4t(uint32_t* r, uint32_t a){
    asm volatile("ldmatrix.sync.aligned.m8n8.x4.trans.shared.b16 {%0,%1,%2,%3},[%4];\n"
        : "=r"(r[0]),"=r"(r[1]),"=r"(r[2]),"=r"(r[3]) : "r"(a));
}
__device__ __forceinline__ void mma16816(float* d, const uint32_t* a, const uint32_t* b)
{
    asm volatile(
        "mma.sync.aligned.m16n8k16.row.col.f32.bf16.bf16.f32 "
        "{%0,%1,%2,%3},{%4,%5,%6,%7},{%8,%9},{%0,%1,%2,%3};\n"
        : "+f"(d[0]), "+f"(d[1]), "+f"(d[2]), "+f"(d[3])
        : "r"(a[0]), "r"(a[1]), "r"(a[2]), "r"(a[3]), "r"(b[0]), "r"(b[1]));
}
__device__ __forceinline__ void mma16816h(float* d, const uint32_t* a, const uint32_t* b)
{
    asm volatile(
        "mma.sync.aligned.m16n8k16.row.col.f32.f16.f16.f32 "
        "{%0,%1,%2,%3},{%4,%5,%6,%7},{%8,%9},{%0,%1,%2,%3};\n"
        : "+f"(d[0]), "+f"(d[1]), "+f"(d[2]), "+f"(d[3])
        : "r"(a[0]), "r"(a[1]), "r"(a[2]), "r"(a[3]), "r"(b[0]), "r"(b[1]));
}

// K-major tile swizzle: 128 rows x 32 elems (64B/row). Conflict-free for
// cp.async writes and ldmatrix reads.
__device__ __forceinline__ uint32_t swzA(int r, int kcol)
{
    const int line = r >> 1;
    const int cc = ((r & 1) << 2) | (kcol >> 3);
    return (uint32_t)(line * 128 + ((cc ^ (line & 7)) << 4));
}

// ---------------- kernel: embedding+LN (blocks < NTOK) + weight split (rest) --
__global__ void embed_ln_split_kernel(const int* __restrict__ inp,
                                      const float* __restrict__ wemb,
                                      const float* __restrict__ pemb,
                                      const float* __restrict__ gamma,
                                      const float* __restrict__ beta,
                                      const float* __restrict__ wq,
                                      const float* __restrict__ wk,
                                      const float* __restrict__ wv)
{
    const int b = blockIdx.x;
    const int tid = threadIdx.x;                     // 0..127

    if (b >= NTOK) {
        // ---- weight split: 512 elems per block ----
        const int i0 = (b - NTOK) * 512 + tid * 4;
        #pragma unroll
        for (int j = 0; j < 4; j++) {
            const int i = i0 + j;
            const int slot = i / (DIM*DIM);
            const int off  = i - slot * (DIM*DIM);
            if (slot == 2) {
                __half h, l;
                split2h(wv[off], h, l);
                ((__half*)g_wh)[i] = h; ((__half*)g_wl)[i] = l;
            } else {
                const float* src = (slot == 0) ? wq : wk;
                bf16 h, l;
                split2(src[off], h, l);
                g_wh[i] = h; g_wl[i] = l;
            }
        }
        return;
    }

    const int tok = b;
    const int s   = tok & (SEQ - 1);
    const int id  = inp[tok];

    const float4 w = ((const float4*)(wemb + (long long)id * DIM))[tid];
    const float4 p = ((const float4*)(pemb + (long long)s  * DIM))[tid];
    float4 e;
    e.x = w.x + p.x; e.y = w.y + p.y; e.z = w.z + p.z; e.w = w.w + p.w;

    float sum = e.x + e.y + e.z + e.w;
    float sq  = e.x*e.x + e.y*e.y + e.z*e.z + e.w*e.w;

    __shared__ float sS[4], sQ[4];
    #pragma unroll
    for (int o = 16; o > 0; o >>= 1) {
        sum += __shfl_xor_sync(0xFFFFFFFFu, sum, o);
        sq  += __shfl_xor_sync(0xFFFFFFFFu, sq,  o);
    }
    if ((tid & 31) == 0) { sS[tid >> 5] = sum; sQ[tid >> 5] = sq; }
    __syncthreads();
    sum = sS[0] + sS[1] + sS[2] + sS[3];
    sq  = sQ[0] + sQ[1] + sQ[2] + sQ[3];

    const float mean = sum * (1.0f / DIM);
    const float var  = sq  * (1.0f / DIM) - mean * mean;
    const float inv  = rsqrtf(var + 1e-5f);

    const float4 ga = ((const float4*)gamma)[tid];
    const float4 be = ((const float4*)beta)[tid];
    float o0 = (e.x - mean) * inv * ga.x + be.x;
    float o1 = (e.y - mean) * inv * ga.y + be.y;
    float o2 = (e.z - mean) * inv * ga.z + be.z;
    float o3 = (e.w - mean) * inv * ga.w + be.w;

    bf16 h0,h1,h2,h3,l0,l1,l2,l3;
    split2(o0,h0,l0); split2(o1,h1,l1); split2(o2,h2,l2); split2(o3,h3,l3);
    const long long base = (long long)tok * DIM + tid * 4;
    *(__nv_bfloat162*)&g_xh[base]   = __nv_bfloat162(h0,h1);
    *(__nv_bfloat162*)&g_xh[base+2] = __nv_bfloat162(h2,h3);
    *(__nv_bfloat162*)&g_xl[base]   = __nv_bfloat162(l0,l1);
    *(__nv_bfloat162*)&g_xl[base+2] = __nv_bfloat162(l2,l3);
    *(__half2*)&g_xf[base]   = __half2(__float2half_rn(o0), __float2half_rn(o1));
    *(__half2*)&g_xf[base+2] = __half2(__float2half_rn(o2), __float2half_rn(o3));
}

// ---------------------------------------------------------------------------
// GEMM body (device fn): C[M,N] = A[M,K] * B.  (R6-proven loop: compute THEN load.)
//   BKN=0 : B global [N][K] -> ldmatrix; BKN=1 : B global [K][N] -> ldmatrix.trans
//   OSPLIT: 0 = fp32 C; 1 = bf16 hi/lo C; 2 = fp16 single C (-> g_vf)
//   PROJ: 0 = generic batched; 1 = Q/K projection; 2 = V projection
//   AVM : 0 = bf16 3-pass; 1 = f16 2-pass; 2 = f16 1-pass
// QK instance (OSPLIT==0 && BKN==0) scales C by 1/sqrt(512) at store.
// 128x128x32 tiles, 256 thr, 3-stage cp.async, 2 CTAs/SM.
// ---------------------------------------------------------------------------
template<int BKN, int OSPLIT, int PROJ, int AVM>
__device__ __forceinline__ void
gemm_body(const bf16* __restrict__ Ah_g, const bf16* __restrict__ Al_g,
          const bf16* __restrict__ Bh_g, const bf16* __restrict__ Bl_g,
          float* __restrict__ Cf, bf16* __restrict__ Ch_p, bf16* __restrict__ Cl_p,
          int K, int lda, int ldb, int ldc,
          long long sA, long long sB, long long sC, int z, char* smem)
{
    constexpr int S = 3;
    constexpr int MATSZ = 8192;
    constexpr int STAGE = 4 * MATSZ;        // 32KB

    const uint32_t sbase = smem_u32(smem);

    const int tid  = threadIdx.x;
    const int warp = tid >> 5, lane = tid & 31;

    const bf16 *Ah, *Al, *Bh, *Bl;
    bf16 *Ch, *Cl;
    if (PROJ == 1) {
        Ah = Ah_g + (long long)blockIdx.y * 128 * lda;
        Al = Al_g + (long long)blockIdx.y * 128 * lda;
        Bh = g_wh + z * (DIM*DIM) + blockIdx.x * 128;
        Bl = g_wl + z * (DIM*DIM) + blockIdx.x * 128;
        Ch = (z == 0) ? g_qh : g_kh;
        Cl = (z == 0) ? g_ql : g_kl;
    } else if (PROJ == 2) {
        Ah = (const bf16*)g_xf + (long long)blockIdx.y * 128 * lda;
        Al = nullptr;
        Bh = g_wh + 2 * (DIM*DIM) + blockIdx.x * 128;   // fp16 bits
        Bl = g_wl + 2 * (DIM*DIM) + blockIdx.x * 128;
        Ch = nullptr; Cl = nullptr;
    } else {
        Ah = Ah_g + z * sA + (long long)blockIdx.y * 128 * lda;
        Al = (AVM == 0) ? (Al_g + z * sA + (long long)blockIdx.y * 128 * lda) : nullptr;
        if (BKN == 0) { Bh = Bh_g + z*sB + (long long)blockIdx.x * 128 * ldb;
                        Bl = Bl_g + z*sB + (long long)blockIdx.x * 128 * ldb; }
        else          { Bh = Bh_g + z*sB + blockIdx.x * 128;
                        Bl = (AVM == 2) ? nullptr : (Bl_g + z*sB + blockIdx.x * 128); }
        Ch = Ch_p; Cl = Cl_p;
    }

    const int wm = (warp >> 2) * 64;
    const int wn = (warp & 3) * 32;

    float acc[4][4][4];
    #pragma unroll
    for (int i = 0; i < 4; i++)
        #pragma unroll
        for (int j = 0; j < 4; j++)
            #pragma unroll
            for (int c = 0; c < 4; c++) acc[i][j][c] = 0.0f;

    auto load_tile = [&](int s, int kt) {
        const uint32_t aOff  = sbase + s * STAGE;
        const uint32_t alOff = aOff + MATSZ;
        const uint32_t bOff  = aOff + 2*MATSZ;
        const uint32_t blOff = bOff + MATSZ;
        {
            const int r  = tid >> 1;
            const int cb = (tid & 1) * 2;
            #pragma unroll
            for (int j = 0; j < 2; j++) {
                const int c = cb + j;
                const long long go = (long long)r * lda + kt + c * 8;
                const uint32_t so = swzA(r, c * 8);
                cp16(aOff  + so, Ah + go);
                if (AVM == 0) cp16(alOff + so, Al + go);
            }
        }
        if (BKN == 0) {
            const int r  = tid >> 1;
            const int cb = (tid & 1) * 2;
            #pragma unroll
            for (int j = 0; j < 2; j++) {
                const int c = cb + j;
                const long long go = (long long)r * ldb + kt + c * 8;
                const uint32_t so = swzA(r, c * 8);
                cp16(bOff  + so, Bh + go);
                cp16(blOff + so, Bl + go);
            }
        } else {
            const int k  = tid >> 3;
            const int cb = (tid & 7) * 2;
            #pragma unroll
            for (int j = 0; j < 2; j++) {
                const int c = cb + j;
                const long long go = (long long)(kt + k) * ldb + c * 8;
                const uint32_t so = (uint32_t)(k * 256 + ((c ^ (k & 7)) * 16));
                cp16(bOff  + so, Bh + go);
                if (AVM != 2) cp16(blOff + so, Bl + go);
            }
        }
    };

    auto compute_tile = [&](int s) {
        const uint32_t aB  = sbase + s * STAGE;
        const uint32_t alB = aB + MATSZ;
        const uint32_t bB  = aB + 2*MATSZ;
        const uint32_t blB = bB + MATSZ;
        const int g = lane >> 3, idx = lane & 7;
        #pragma unroll
        for (int ks = 0; ks < 2; ks++) {
            const int k0 = ks * 16;
            uint32_t aH[4][4], aL[4][4], bH[4][2], bL[4][2];
            {
                const int arow = wm + (g & 1) * 8 + idx;
                const int acol = k0 + (g >> 1) * 8;
                #pragma unroll
                for (int mt = 0; mt < 4; mt++) {
                    const uint32_t so = swzA(arow + mt*16, acol);
                    ldsm4(aH[mt], aB  + so);
                    if (AVM == 0) ldsm4(aL[mt], alB + so);
                }
            }
            if (BKN == 0) {
                const int brow = wn + (g >> 1) * 8 + idx;
                const int bcol = k0 + (g & 1) * 8;
                #pragma unroll
                for (int p = 0; p < 2; p++) {
                    const uint32_t so = swzA(brow + p*16, bcol);
                    uint32_t r[4];
                    ldsm4(r, bB + so);
                    bH[2*p][0]=r[0]; bH[2*p][1]=r[1]; bH[2*p+1][0]=r[2]; bH[2*p+1][1]=r[3];
                    ldsm4(r, blB + so);
                    bL[2*p][0]=r[0]; bL[2*p][1]=r[1]; bL[2*p+1][0]=r[2]; bL[2*p+1][1]=r[3];
                }
            } else {
                const int krow = k0 + (g & 1) * 8 + idx;
                #pragma unroll
                for (int p = 0; p < 2; p++) {
                    const int nch = (wn + p*16 + (g >> 1) * 8) >> 3;
                    const uint32_t so = (uint32_t)(krow * 256 + ((nch ^ (krow & 7)) * 16));
                    uint32_t r[4];
                    ldsm4t(r, bB + so);
                    bH[2*p][0]=r[0]; bH[2*p][1]=r[1]; bH[2*p+1][0]=r[2]; bH[2*p+1][1]=r[3];
                    if (AVM != 2) {
                        ldsm4t(r, blB + so);
                        bL[2*p][0]=r[0]; bL[2*p][1]=r[1]; bL[2*p+1][0]=r[2]; bL[2*p+1][1]=r[3];
                    }
                }
            }
            if (AVM == 0) {
                #pragma unroll
                for (int mt = 0; mt < 4; mt++)
                    #pragma unroll
                    for (int nt = 0; nt < 4; nt++) mma16816(acc[mt][nt], aH[mt], bH[nt]);
                #pragma unroll
                for (int mt = 0; mt < 4; mt++)
                    #pragma unroll
                    for (int nt = 0; nt < 4; nt++) mma16816(acc[mt][nt], aL[mt], bH[nt]);
                #pragma unroll
                for (int mt = 0; mt < 4; mt++)
                    #pragma unroll
                    for (int nt = 0; nt < 4; nt++) mma16816(acc[mt][nt], aH[mt], bL[nt]);
            } else if (AVM == 1) {
                #pragma unroll
                for (int mt = 0; mt < 4; mt++)
                    #pragma unroll
                    for (int nt = 0; nt < 4; nt++) mma16816h(acc[mt][nt], aH[mt], bH[nt]);
                #pragma unroll
                for (int mt = 0; mt < 4; mt++)
                    #pragma unroll
                    for (int nt = 0; nt < 4; nt++) mma16816h(acc[mt][nt], aH[mt], bL[nt]);
            } else {
                #pragma unroll
                for (int mt = 0; mt < 4; mt++)
                    #pragma unroll
                    for (int nt = 0; nt < 4; nt++) mma16816h(acc[mt][nt], aH[mt], bH[nt]);
            }
        }
    };

    const int T = K / 32;
    #pragma unroll
    for (int s = 0; s < S - 1; s++) { load_tile(s, s * 32); cp_commit(); }

    for (int t = 0; t < T; t++) {
        cp_wait<S - 2>();
        __syncthreads();
        compute_tile(t % S);
        const int tn = t + S - 1;
        if (tn < T) load_tile(tn % S, tn * 32);
        cp_commit();
    }

    const int r  = lane >> 2;
    const int c2 = (lane & 3) * 2;
    if (OSPLIT == 0) {
        // QK instance folds the softmax scale into the store
        const float cs = (BKN == 0) ? 0.044194173824159216f : 1.0f;
        float* C = Cf + z * sC + (long long)blockIdx.y * 128 * ldc + blockIdx.x * 128;
        #pragma unroll
        for (int mt = 0; mt < 4; mt++)
            #pragma unroll
            for (int nt = 0; nt < 4; nt++) {
                const long long row = wm + mt * 16 + r;
                const int col = wn + nt * 8 + c2;
                *(float2*)&C[row * ldc + col]       = make_float2(acc[mt][nt][0]*cs, acc[mt][nt][1]*cs);
                *(float2*)&C[(row + 8) * ldc + col] = make_float2(acc[mt][nt][2]*cs, acc[mt][nt][3]*cs);
            }
    } else if (OSPLIT == 2) {
        __half* CH = g_vf + (long long)blockIdx.y * 128 * ldc + blockIdx.x * 128;
        #pragma unroll
        for (int mt = 0; mt < 4; mt++)
            #pragma unroll
            for (int nt = 0; nt < 4; nt++) {
                const long long row = wm + mt * 16 + r;
                const int col = wn + nt * 8 + c2;
                *(__half2*)&CH[row * ldc + col] =
                    __half2(__float2half_rn(acc[mt][nt][0]), __float2half_rn(acc[mt][nt][1]));
                *(__half2*)&CH[(row+8) * ldc + col] =
                    __half2(__float2half_rn(acc[mt][nt][2]), __float2half_rn(acc[mt][nt][3]));
            }
    } else {
        bf16* CH = Ch + (long long)blockIdx.y * 128 * ldc + blockIdx.x * 128;
        bf16* CL = Cl + (long long)blockIdx.y * 128 * ldc + blockIdx.x * 128;
        if (PROJ == 0) { CH += z * sC; CL += z * sC; }
        #pragma unroll
        for (int mt = 0; mt < 4; mt++)
            #pragma unroll
            for (int nt = 0; nt < 4; nt++) {
                const long long row = wm + mt * 16 + r;
                const int col = wn + nt * 8 + c2;
                bf16 h0,h1,l0,l1;
                split2(acc[mt][nt][0], h0, l0); split2(acc[mt][nt][1], h1, l1);
                *(__nv_bfloat162*)&CH[row * ldc + col] = __nv_bfloat162(h0,h1);
                *(__nv_bfloat162*)&CL[row * ldc + col] = __nv_bfloat162(l0,l1);
                split2(acc[mt][nt][2], h0, l0); split2(acc[mt][nt][3], h1, l1);
                *(__nv_bfloat162*)&CH[(row+8) * ldc + col] = __nv_bfloat162(h0,h1);
                *(__nv_bfloat162*)&CL[(row+8) * ldc + col] = __nv_bfloat162(l0,l1);
            }
    }
}

// ---------------- GEMM kernels ----------------
template<int BKN, int OSPLIT, int PROJ, int AVM>
__global__ void __launch_bounds__(256, 2)
gemm2(const bf16* __restrict__ Ah_g, const bf16* __restrict__ Al_g,
      const bf16* __restrict__ Bh_g, const bf16* __restrict__ Bl_g,
      float* __restrict__ Cf, bf16* __restrict__ Ch_p, bf16* __restrict__ Cl_p,
      int K, int lda, int ldb, int ldc,
      long long sA, long long sB, long long sC)
{
    extern __shared__ char smem[];
    gemm_body<BKN,OSPLIT,PROJ,AVM>(Ah_g, Al_g, Bh_g, Bl_g, Cf, Ch_p, Cl_p,
                                   K, lda, ldb, ldc, sA, sB, sC, blockIdx.z, smem);
}

// merged tri-projection: z 0,1 = Q/K (bf16 3-pass); z 2 = V (fp16 2-pass)
__global__ void __launch_bounds__(256, 2)
proj_all_kernel(const bf16* __restrict__ xh, const bf16* __restrict__ xl)
{
    extern __shared__ char smem[];
    const int z = blockIdx.z;
    if (z < 2) {
        gemm_body<1,1,1,0>(xh, xl, nullptr, nullptr, nullptr, nullptr, nullptr,
                           DIM, DIM, DIM, DIM, 0, 0, 0, z, smem);
    } else {
        gemm_body<1,2,2,1>(nullptr, nullptr, nullptr, nullptr, nullptr, nullptr, nullptr,
                           DIM, DIM, DIM, DIM, 0, 0, 0, z, smem);
    }
}

// ---------------- kernel: softmax -> attn fp16 (reverse row order for L2) ----
// Scores are pre-scaled by QK epilogue.
__global__ void softmax_kernel(const float* __restrict__ Sc)
{
    const long long lin = (long long)blockIdx.y * SEQ + blockIdx.x;
    const long long row = (long long)BQ * SEQ - 1 - lin;   // reverse: read hottest first
    const float4* p = (const float4*)(Sc + row * SEQ);
    const int tid = threadIdx.x;
    const int warp = tid >> 5, lane = tid & 31;

    float4 v = p[tid];

    __shared__ float redM[8], redS[8];

    float mx = fmaxf(fmaxf(v.x, v.y), fmaxf(v.z, v.w));
    #pragma unroll
    for (int o = 16; o > 0; o >>= 1) mx = fmaxf(mx, __shfl_xor_sync(0xFFFFFFFFu, mx, o));
    if (lane == 0) redM[warp] = mx;
    __syncthreads();
    mx = redM[0];
    #pragma unroll
    for (int i = 1; i < 8; i++) mx = fmaxf(mx, redM[i]);

    float e0 = expf(v.x - mx), e1 = expf(v.y - mx);
    float e2 = expf(v.z - mx), e3 = expf(v.w - mx);
    float sum = e0 + e1 + e2 + e3;
    #pragma unroll
    for (int o = 16; o > 0; o >>= 1) sum += __shfl_xor_sync(0xFFFFFFFFu, sum, o);
    if (lane == 0) redS[warp] = sum;
    __syncthreads();
    sum = redS[0]+redS[1]+redS[2]+redS[3]+redS[4]+redS[5]+redS[6]+redS[7];

    const float inv = 1.0f / sum;
    const long long base = row * SEQ + tid * 4;
    *(__half2*)&g_af[base]   = __half2(__float2half_rn(e0*inv), __float2half_rn(e1*inv));
    *(__half2*)&g_af[base+2] = __half2(__float2half_rn(e2*inv), __float2half_rn(e3*inv));
}

// ---------------------------------------------------------------------------
extern "C" void kernel_launch(void* const* d_in, const int* in_sizes, int n_in,
                              void* d_out, int out_size)
{
    const int*   inp   = (const int*)  d_in[0];
    const float* wemb  = (const float*)d_in[1];
    const float* pemb  = (const float*)d_in[2];
    const float* gamma = (const float*)d_in[3];
    const float* beta  = (const float*)d_in[4];
    const float* Wk    = (const float*)d_in[5];
    const float* Wq    = (const float*)d_in[6];
    const float* Wv    = (const float*)d_in[7];
    float* out = (float*)d_out;

    bf16 *xh,*xl,*qh,*ql,*kh,*kl;
    __half *vf,*af;
    float *ps;
    cudaGetSymbolAddress((void**)&xh, g_xh); cudaGetSymbolAddress((void**)&xl, g_xl);
    cudaGetSymbolAddress((void**)&qh, g_qh); cudaGetSymbolAddress((void**)&ql, g_ql);
    cudaGetSymbolAddress((void**)&kh, g_kh); cudaGetSymbolAddress((void**)&kl, g_kl);
    cudaGetSymbolAddress((void**)&vf, g_vf);
    cudaGetSymbolAddress((void**)&af, g_af);
    cudaGetSymbolAddress((void**)&ps, g_s);

    const int SMEMSZ = 3 * 32768;  // 98304 B -> 2 CTAs/SM
    cudaFuncSetAttribute(proj_all_kernel, cudaFuncAttributeMaxDynamicSharedMemorySize, SMEMSZ);
    cudaFuncSetAttribute(gemm2<0,0,0,0>, cudaFuncAttributeMaxDynamicSharedMemorySize, SMEMSZ);
    cudaFuncSetAttribute(gemm2<1,0,0,2>, cudaFuncAttributeMaxDynamicSharedMemorySize, SMEMSZ);

    // 1) embedding + layernorm + weight split in ONE launch
    const int splitBlocks = 3 * DIM * DIM / 512;   // 1536
    embed_ln_split_kernel<<<NTOK + splitBlocks, 128>>>(inp, wemb, pemb, gamma, beta,
                                                       Wq, Wk, Wv);

    // 2) ALL projections in one launch (z: 0=Q, 1=K bf16 3-pass; 2=V fp16 2-pass)
    dim3 gproj(DIM/128, NTOK/128, 3);
    proj_all_kernel<<<gproj, 256, SMEMSZ>>>(xh, xl);

    // 3) scores = Q @ K^T (batched, bf16 x3) — scaled at store
    dim3 gsc(SEQ/128, SEQ/128, BQ);
    gemm2<0,0,0,0><<<gsc, 256, SMEMSZ>>>(qh, ql, kh, kl, ps, nullptr, nullptr,
                                         DIM, DIM, DIM, SEQ,
                                         (long long)SEQ*DIM, (long long)SEQ*DIM,
                                         (long long)SEQ*SEQ);

    // 4) softmax (reverse order, L2-hot) -> attn fp16 single
    softmax_kernel<<<dim3(SEQ, BQ), 256>>>(ps);

    // 5) out = attn(fp16) @ V(fp16 single), 1 MMA pass
    dim3 gav(DIM/128, SEQ/128, BQ);
    gemm2<1,0,0,2><<<gav, 256, SMEMSZ>>>((const bf16*)af, nullptr, (const bf16*)vf, nullptr,
                                         out, nullptr, nullptr,
                                         SEQ, SEQ, DIM, DIM,
                                         (long long)SEQ*SEQ, (long long)SEQ*DIM,
                                         (long long)SEQ*DIM);
}

// round 17
// speedup vs baseline: 1.6286x; 1.0016x over previous
#include <cuda_runtime.h>
#include <cuda_bf16.h>
#include <cuda_fp16.h>
#include <stdint.h>

#define BQ   32
#define SEQ  1024
#define DIM  512
#define NTOK (BQ*SEQ)
typedef __nv_bfloat16 bf16;

// ---------------- scratch (device globals; no allocs allowed) ----------------
__device__ bf16 g_xh[NTOK*DIM], g_xl[NTOK*DIM];
__device__ __half g_xf[NTOK*DIM];                 // x as fp16 single (V path)
__device__ bf16 g_qh[NTOK*DIM], g_ql[NTOK*DIM];
__device__ bf16 g_kh[NTOK*DIM], g_kl[NTOK*DIM];
__device__ __half g_vf[NTOK*DIM];                 // V as fp16 single
__device__ __half g_af[(size_t)BQ*SEQ*SEQ];       // attn weights, fp16
__device__ __half g_sp[(size_t)BQ*SEQ*SEQ];       // scores: s*cs - m_tile, fp16
__device__ float  g_stats[(size_t)BQ*8*SEQ];      // per (z, tilecol, row) tile max
__device__ bf16 g_wh[3*DIM*DIM], g_wl[3*DIM*DIM]; // slots q,k bf16; slot v fp16 bits

__device__ __forceinline__ void split2(float x, bf16& h, bf16& l)
{
    h = __float2bfloat16(x);
    l = __float2bfloat16(x - __bfloat162float(h));
}
__device__ __forceinline__ void split2h(float x, __half& h, __half& l)
{
    h = __float2half_rn(x);
    l = __float2half_rn(x - __half2float(h));
}

// ---------------- PTX helpers ----------------
__device__ __forceinline__ uint32_t smem_u32(const void* p){
    return (uint32_t)__cvta_generic_to_shared(p);
}
__device__ __forceinline__ void cp16(uint32_t s, const void* g){
    asm volatile("cp.async.cg.shared.global [%0],[%1],16;\n" :: "r"(s), "l"(g));
}
__device__ __forceinline__ void cp_commit(){ asm volatile("cp.async.commit_group;\n" ::: "memory"); }
template<int N> __device__ __forceinline__ void cp_wait(){
    asm volatile("cp.async.wait_group %0;\n" :: "n"(N) : "memory");
}
__device__ __forceinline__ void ldsm4(uint32_t* r, uint32_t a){
    asm volatile("ldmatrix.sync.aligned.m8n8.x4.shared.b16 {%0,%1,%2,%3},[%4];\n"
        : "=r"(r[0]),"=r"(r[1]),"=r"(r[2]),"=r"(r[3]) : "r"(a));
}
__device__ __forceinline__ void ldsm4t(uint32_t* r, uint32_t a){
    asm volatile("ldmatrix.sync.aligned.m8n8.x4.trans.shared.b16 {%0,%1,%2,%3},[%4];\n"
        : "=r"(r[0]),"=r"(r[1]),"=r"(r[2]),"=r"(r[3]) : "r"(a));
}
__device__ __forceinline__ void mma16816(float* d, const uint32_t* a, const uint32_t* b)
{
    asm volatile(
        "mma.sync.aligned.m16n8k16.row.col.f32.bf16.bf16.f32 "
        "{%0,%1,%2,%3},{%4,%5,%6,%7},{%8,%9},{%0,%1,%2,%3};\n"
        : "+f"(d[0]), "+f"(d[1]), "+f"(d[2]), "+f"(d[3])
        : "r"(a[0]), "r"(a[1]), "r"(a[2]), "r"(a[3]), "r"(b[0]), "r"(b[1]));
}
__device__ __forceinline__ void mma16816h(float* d, const uint32_t* a, const uint32_t* b)
{
    asm volatile(
        "mma.sync.aligned.m16n8k16.row.col.f32.f16.f16.f32 "
        "{%0,%1,%2,%3},{%4,%5,%6,%7},{%8,%9},{%0,%1,%2,%3};\n"
        : "+f"(d[0]), "+f"(d[1]), "+f"(d[2]), "+f"(d[3])
        : "r"(a[0]), "r"(a[1]), "r"(a[2]), "r"(a[3]), "r"(b[0]), "r"(b[1]));
}

// K-major tile swizzle: 128 rows x 32 elems (64B/row). Conflict-free.
__device__ __forceinline__ uint32_t swzA(int r, int kcol)
{
    const int line = r >> 1;
    const int cc = ((r & 1) << 2) | (kcol >> 3);
    return (uint32_t)(line * 128 + ((cc ^ (line & 7)) << 4));
}

// ---------------- kernel: embedding+LN (blocks < NTOK) + weight split (rest) --
__global__ void embed_ln_split_kernel(const int* __restrict__ inp,
                                      const float* __restrict__ wemb,
                                      const float* __restrict__ pemb,
                                      const float* __restrict__ gamma,
                                      const float* __restrict__ beta,
                                      const float* __restrict__ wq,
                                      const float* __restrict__ wk,
                                      const float* __restrict__ wv)
{
    const int b = blockIdx.x;
    const int tid = threadIdx.x;                     // 0..127

    if (b >= NTOK) {
        const int i0 = (b - NTOK) * 512 + tid * 4;
        #pragma unroll
        for (int j = 0; j < 4; j++) {
            const int i = i0 + j;
            const int slot = i / (DIM*DIM);
            const int off  = i - slot * (DIM*DIM);
            if (slot == 2) {
                __half h, l;
                split2h(wv[off], h, l);
                ((__half*)g_wh)[i] = h; ((__half*)g_wl)[i] = l;
            } else {
                const float* src = (slot == 0) ? wq : wk;
                bf16 h, l;
                split2(src[off], h, l);
                g_wh[i] = h; g_wl[i] = l;
            }
        }
        return;
    }

    const int tok = b;
    const int s   = tok & (SEQ - 1);
    const int id  = inp[tok];

    const float4 w = ((const float4*)(wemb + (long long)id * DIM))[tid];
    const float4 p = ((const float4*)(pemb + (long long)s  * DIM))[tid];
    float4 e;
    e.x = w.x + p.x; e.y = w.y + p.y; e.z = w.z + p.z; e.w = w.w + p.w;

    float sum = e.x + e.y + e.z + e.w;
    float sq  = e.x*e.x + e.y*e.y + e.z*e.z + e.w*e.w;

    __shared__ float sS[4], sQ[4];
    #pragma unroll
    for (int o = 16; o > 0; o >>= 1) {
        sum += __shfl_xor_sync(0xFFFFFFFFu, sum, o);
        sq  += __shfl_xor_sync(0xFFFFFFFFu, sq,  o);
    }
    if ((tid & 31) == 0) { sS[tid >> 5] = sum; sQ[tid >> 5] = sq; }
    __syncthreads();
    sum = sS[0] + sS[1] + sS[2] + sS[3];
    sq  = sQ[0] + sQ[1] + sQ[2] + sQ[3];

    const float mean = sum * (1.0f / DIM);
    const float var  = sq  * (1.0f / DIM) - mean * mean;
    const float inv  = rsqrtf(var + 1e-5f);

    const float4 ga = ((const float4*)gamma)[tid];
    const float4 be = ((const float4*)beta)[tid];
    float o0 = (e.x - mean) * inv * ga.x + be.x;
    float o1 = (e.y - mean) * inv * ga.y + be.y;
    float o2 = (e.z - mean) * inv * ga.z + be.z;
    float o3 = (e.w - mean) * inv * ga.w + be.w;

    bf16 h0,h1,h2,h3,l0,l1,l2,l3;
    split2(o0,h0,l0); split2(o1,h1,l1); split2(o2,h2,l2); split2(o3,h3,l3);
    const long long base = (long long)tok * DIM + tid * 4;
    *(__nv_bfloat162*)&g_xh[base]   = __nv_bfloat162(h0,h1);
    *(__nv_bfloat162*)&g_xh[base+2] = __nv_bfloat162(h2,h3);
    *(__nv_bfloat162*)&g_xl[base]   = __nv_bfloat162(l0,l1);
    *(__nv_bfloat162*)&g_xl[base+2] = __nv_bfloat162(l2,l3);
    *(__half2*)&g_xf[base]   = __half2(__float2half_rn(o0), __float2half_rn(o1));
    *(__half2*)&g_xf[base+2] = __half2(__float2half_rn(o2), __float2half_rn(o3));
}

// ---------------------------------------------------------------------------
// GEMM body: C[M,N] = A[M,K] * B.  (R6-proven loop: compute THEN load.)
//   BKN=0 : B [N][K] -> ldmatrix; BKN=1 : B [K][N] -> ldmatrix.trans
//   OSPLIT: 0 = fp32 C; 1 = bf16 hi/lo C; 2 = fp16 single C (-> g_vf);
//           3 = SCORES: fp16 (s*cs - rowmax_tile) -> g_sp, rowmax -> g_stats
//   PROJ: 0 = generic batched; 1 = Q/K projection; 2 = V projection
//   AVM : 0 = bf16 3-pass; 1 = f16 2-pass; 2 = f16 1-pass
// 128x128x32 tiles, 256 thr, 3-stage cp.async, 2 CTAs/SM.
// ---------------------------------------------------------------------------
template<int BKN, int OSPLIT, int PROJ, int AVM>
__device__ __forceinline__ void
gemm_body(const bf16* __restrict__ Ah_g, const bf16* __restrict__ Al_g,
          const bf16* __restrict__ Bh_g, const bf16* __restrict__ Bl_g,
          float* __restrict__ Cf, bf16* __restrict__ Ch_p, bf16* __restrict__ Cl_p,
          int K, int lda, int ldb, int ldc,
          long long sA, long long sB, long long sC, int z, char* smem)
{
    constexpr int S = 3;
    constexpr int MATSZ = 8192;
    constexpr int STAGE = 4 * MATSZ;        // 32KB

    const uint32_t sbase = smem_u32(smem);

    const int tid  = threadIdx.x;
    const int warp = tid >> 5, lane = tid & 31;

    const bf16 *Ah, *Al, *Bh, *Bl;
    bf16 *Ch, *Cl;
    if (PROJ == 1) {
        Ah = Ah_g + (long long)blockIdx.y * 128 * lda;
        Al = Al_g + (long long)blockIdx.y * 128 * lda;
        Bh = g_wh + z * (DIM*DIM) + blockIdx.x * 128;
        Bl = g_wl + z * (DIM*DIM) + blockIdx.x * 128;
        Ch = (z == 0) ? g_qh : g_kh;
        Cl = (z == 0) ? g_ql : g_kl;
    } else if (PROJ == 2) {
        Ah = (const bf16*)g_xf + (long long)blockIdx.y * 128 * lda;
        Al = nullptr;
        Bh = g_wh + 2 * (DIM*DIM) + blockIdx.x * 128;   // fp16 bits
        Bl = g_wl + 2 * (DIM*DIM) + blockIdx.x * 128;
        Ch = nullptr; Cl = nullptr;
    } else {
        Ah = Ah_g + z * sA + (long long)blockIdx.y * 128 * lda;
        Al = (AVM == 0) ? (Al_g + z * sA + (long long)blockIdx.y * 128 * lda) : nullptr;
        if (BKN == 0) { Bh = Bh_g + z*sB + (long long)blockIdx.x * 128 * ldb;
                        Bl = Bl_g + z*sB + (long long)blockIdx.x * 128 * ldb; }
        else          { Bh = Bh_g + z*sB + blockIdx.x * 128;
                        Bl = (AVM == 2) ? nullptr : (Bl_g + z*sB + blockIdx.x * 128); }
        Ch = Ch_p; Cl = Cl_p;
    }

    const int wm = (warp >> 2) * 64;
    const int wn = (warp & 3) * 32;

    float acc[4][4][4];
    #pragma unroll
    for (int i = 0; i < 4; i++)
        #pragma unroll
        for (int j = 0; j < 4; j++)
            #pragma unroll
            for (int c = 0; c < 4; c++) acc[i][j][c] = 0.0f;

    auto load_tile = [&](int s, int kt) {
        const uint32_t aOff  = sbase + s * STAGE;
        const uint32_t alOff = aOff + MATSZ;
        const uint32_t bOff  = aOff + 2*MATSZ;
        const uint32_t blOff = bOff + MATSZ;
        {
            const int r  = tid >> 1;
            const int cb = (tid & 1) * 2;
            #pragma unroll
            for (int j = 0; j < 2; j++) {
                const int c = cb + j;
                const long long go = (long long)r * lda + kt + c * 8;
                const uint32_t so = swzA(r, c * 8);
                cp16(aOff  + so, Ah + go);
                if (AVM == 0) cp16(alOff + so, Al + go);
            }
        }
        if (BKN == 0) {
            const int r  = tid >> 1;
            const int cb = (tid & 1) * 2;
            #pragma unroll
            for (int j = 0; j < 2; j++) {
                const int c = cb + j;
                const long long go = (long long)r * ldb + kt + c * 8;
                const uint32_t so = swzA(r, c * 8);
                cp16(bOff  + so, Bh + go);
                cp16(blOff + so, Bl + go);
            }
        } else {
            const int k  = tid >> 3;
            const int cb = (tid & 7) * 2;
            #pragma unroll
            for (int j = 0; j < 2; j++) {
                const int c = cb + j;
                const long long go = (long long)(kt + k) * ldb + c * 8;
                const uint32_t so = (uint32_t)(k * 256 + ((c ^ (k & 7)) * 16));
                cp16(bOff  + so, Bh + go);
                if (AVM != 2) cp16(blOff + so, Bl + go);
            }
        }
    };

    auto compute_tile = [&](int s) {
        const uint32_t aB  = sbase + s * STAGE;
        const uint32_t alB = aB + MATSZ;
        const uint32_t bB  = aB + 2*MATSZ;
        const uint32_t blB = bB + MATSZ;
        const int g = lane >> 3, idx = lane & 7;
        #pragma unroll
        for (int ks = 0; ks < 2; ks++) {
            const int k0 = ks * 16;
            uint32_t aH[4][4], aL[4][4], bH[4][2], bL[4][2];
            {
                const int arow = wm + (g & 1) * 8 + idx;
                const int acol = k0 + (g >> 1) * 8;
                #pragma unroll
                for (int mt = 0; mt < 4; mt++) {
                    const uint32_t so = swzA(arow + mt*16, acol);
                    ldsm4(aH[mt], aB  + so);
                    if (AVM == 0) ldsm4(aL[mt], alB + so);
                }
            }
            if (BKN == 0) {
                const int brow = wn + (g >> 1) * 8 + idx;
                const int bcol = k0 + (g & 1) * 8;
                #pragma unroll
                for (int p = 0; p < 2; p++) {
                    const uint32_t so = swzA(brow + p*16, bcol);
                    uint32_t r[4];
                    ldsm4(r, bB + so);
                    bH[2*p][0]=r[0]; bH[2*p][1]=r[1]; bH[2*p+1][0]=r[2]; bH[2*p+1][1]=r[3];
                    ldsm4(r, blB + so);
                    bL[2*p][0]=r[0]; bL[2*p][1]=r[1]; bL[2*p+1][0]=r[2]; bL[2*p+1][1]=r[3];
                }
            } else {
                const int krow = k0 + (g & 1) * 8 + idx;
                #pragma unroll
                for (int p = 0; p < 2; p++) {
                    const int nch = (wn + p*16 + (g >> 1) * 8) >> 3;
                    const uint32_t so = (uint32_t)(krow * 256 + ((nch ^ (krow & 7)) * 16));
                    uint32_t r[4];
                    ldsm4t(r, bB + so);
                    bH[2*p][0]=r[0]; bH[2*p][1]=r[1]; bH[2*p+1][0]=r[2]; bH[2*p+1][1]=r[3];
                    if (AVM != 2) {
                        ldsm4t(r, blB + so);
                        bL[2*p][0]=r[0]; bL[2*p][1]=r[1]; bL[2*p+1][0]=r[2]; bL[2*p+1][1]=r[3];
                    }
                }
            }
            if (AVM == 0) {
                #pragma unroll
                for (int mt = 0; mt < 4; mt++)
                    #pragma unroll
                    for (int nt = 0; nt < 4; nt++) mma16816(acc[mt][nt], aH[mt], bH[nt]);
                #pragma unroll
                for (int mt = 0; mt < 4; mt++)
                    #pragma unroll
                    for (int nt = 0; nt < 4; nt++) mma16816(acc[mt][nt], aL[mt], bH[nt]);
                #pragma unroll
                for (int mt = 0; mt < 4; mt++)
                    #pragma unroll
                    for (int nt = 0; nt < 4; nt++) mma16816(acc[mt][nt], aH[mt], bL[nt]);
            } else if (AVM == 1) {
                #pragma unroll
                for (int mt = 0; mt < 4; mt++)
                    #pragma unroll
                    for (int nt = 0; nt < 4; nt++) mma16816h(acc[mt][nt], aH[mt], bH[nt]);
                #pragma unroll
                for (int mt = 0; mt < 4; mt++)
                    #pragma unroll
                    for (int nt = 0; nt < 4; nt++) mma16816h(acc[mt][nt], aH[mt], bL[nt]);
            } else {
                #pragma unroll
                for (int mt = 0; mt < 4; mt++)
                    #pragma unroll
                    for (int nt = 0; nt < 4; nt++) mma16816h(acc[mt][nt], aH[mt], bH[nt]);
            }
        }
    };

    const int T = K / 32;
    #pragma unroll
    for (int s = 0; s < S - 1; s++) { load_tile(s, s * 32); cp_commit(); }

    for (int t = 0; t < T; t++) {
        cp_wait<S - 2>();
        __syncthreads();
        compute_tile(t % S);
        const int tn = t + S - 1;
        if (tn < T) load_tile(tn % S, tn * 32);
        cp_commit();
    }

    const int r  = lane >> 2;
    const int c2 = (lane & 3) * 2;
    if (OSPLIT == 3) {
        // ---- scores epilogue: per-tile row max + fp16 shifted store ----
        cp_wait<0>();
        __syncthreads();
        float* sred = (float*)smem;              // [4][128]
        const float cs = 0.044194173824159216f;  // 1/sqrt(512)
        #pragma unroll
        for (int mt = 0; mt < 4; mt++)
            #pragma unroll
            for (int nt = 0; nt < 4; nt++)
                #pragma unroll
                for (int i = 0; i < 4; i++) acc[mt][nt][i] *= cs;
        float m8[8];
        #pragma unroll
        for (int mt = 0; mt < 4; mt++) {
            float m0 = -1e30f, m1 = -1e30f;
            #pragma unroll
            for (int nt = 0; nt < 4; nt++) {
                m0 = fmaxf(m0, fmaxf(acc[mt][nt][0], acc[mt][nt][1]));
                m1 = fmaxf(m1, fmaxf(acc[mt][nt][2], acc[mt][nt][3]));
            }
            m8[2*mt] = m0; m8[2*mt+1] = m1;
        }
        #pragma unroll
        for (int s2 = 0; s2 < 8; s2++) {
            m8[s2] = fmaxf(m8[s2], __shfl_xor_sync(0xFFFFFFFFu, m8[s2], 1));
            m8[s2] = fmaxf(m8[s2], __shfl_xor_sync(0xFFFFFFFFu, m8[s2], 2));
        }
        if ((lane & 3) == 0) {
            #pragma unroll
            for (int mt = 0; mt < 4; mt++) {
                sred[(warp & 3) * 128 + wm + mt*16 + r]     = m8[2*mt];
                sred[(warp & 3) * 128 + wm + mt*16 + r + 8] = m8[2*mt+1];
            }
        }
        __syncthreads();
        float rm[8];
        #pragma unroll
        for (int mt = 0; mt < 4; mt++) {
            const int lr = wm + mt*16 + r;
            rm[2*mt]   = fmaxf(fmaxf(sred[lr],   sred[128+lr]),   fmaxf(sred[256+lr],   sred[384+lr]));
            rm[2*mt+1] = fmaxf(fmaxf(sred[lr+8], sred[128+lr+8]), fmaxf(sred[256+lr+8], sred[384+lr+8]));
        }
        if ((warp & 3) == 0 && (lane & 3) == 0) {
            float* st = g_stats + ((size_t)(z * 8 + blockIdx.x)) * SEQ + (size_t)blockIdx.y * 128;
            #pragma unroll
            for (int mt = 0; mt < 4; mt++) {
                st[wm + mt*16 + r]     = rm[2*mt];
                st[wm + mt*16 + r + 8] = rm[2*mt+1];
            }
        }
        __half* P = g_sp + (size_t)z * SEQ * SEQ
                  + ((size_t)blockIdx.y * 128) * (size_t)SEQ + blockIdx.x * 128;
        #pragma unroll
        for (int mt = 0; mt < 4; mt++)
            #pragma unroll
            for (int nt = 0; nt < 4; nt++) {
                const size_t row = wm + mt*16 + r;
                const int col = wn + nt*8 + c2;
                *(__half2*)&P[row * SEQ + col] =
                    __floats2half2_rn(acc[mt][nt][0]-rm[2*mt], acc[mt][nt][1]-rm[2*mt]);
                *(__half2*)&P[(row+8) * SEQ + col] =
                    __floats2half2_rn(acc[mt][nt][2]-rm[2*mt+1], acc[mt][nt][3]-rm[2*mt+1]);
            }
    } else if (OSPLIT == 0) {
        float* C = Cf + z * sC + (long long)blockIdx.y * 128 * ldc + blockIdx.x * 128;
        #pragma unroll
        for (int mt = 0; mt < 4; mt++)
            #pragma unroll
            for (int nt = 0; nt < 4; nt++) {
                const long long row = wm + mt * 16 + r;
                const int col = wn + nt * 8 + c2;
                *(float2*)&C[row * ldc + col]       = make_float2(acc[mt][nt][0], acc[mt][nt][1]);
                *(float2*)&C[(row + 8) * ldc + col] = make_float2(acc[mt][nt][2], acc[mt][nt][3]);
            }
    } else if (OSPLIT == 2) {
        __half* CH = g_vf + (long long)blockIdx.y * 128 * ldc + blockIdx.x * 128;
        #pragma unroll
        for (int mt = 0; mt < 4; mt++)
            #pragma unroll
            for (int nt = 0; nt < 4; nt++) {
                const long long row = wm + mt * 16 + r;
                const int col = wn + nt * 8 + c2;
                *(__half2*)&CH[row * ldc + col] =
                    __half2(__float2half_rn(acc[mt][nt][0]), __float2half_rn(acc[mt][nt][1]));
                *(__half2*)&CH[(row+8) * ldc + col] =
                    __half2(__float2half_rn(acc[mt][nt][2]), __float2half_rn(acc[mt][nt][3]));
            }
    } else {
        bf16* CH = Ch + (long long)blockIdx.y * 128 * ldc + blockIdx.x * 128;
        bf16* CL = Cl + (long long)blockIdx.y * 128 * ldc + blockIdx.x * 128;
        if (PROJ == 0) { CH += z * sC; CL += z * sC; }
        #pragma unroll
        for (int mt = 0; mt < 4; mt++)
            #pragma unroll
            for (int nt = 0; nt < 4; nt++) {
                const long long row = wm + mt * 16 + r;
                const int col = wn + nt * 8 + c2;
                bf16 h0,h1,l0,l1;
                split2(acc[mt][nt][0], h0, l0); split2(acc[mt][nt][1], h1, l1);
                *(__nv_bfloat162*)&CH[row * ldc + col] = __nv_bfloat162(h0,h1);
                *(__nv_bfloat162*)&CL[row * ldc + col] = __nv_bfloat162(l0,l1);
                split2(acc[mt][nt][2], h0, l0); split2(acc[mt][nt][3], h1, l1);
                *(__nv_bfloat162*)&CH[(row+8) * ldc + col] = __nv_bfloat162(h0,h1);
                *(__nv_bfloat162*)&CL[(row+8) * ldc + col] = __nv_bfloat162(l0,l1);
            }
    }
}

// ---------------- GEMM kernels ----------------
template<int BKN, int OSPLIT, int PROJ, int AVM>
__global__ void __launch_bounds__(256, 2)
gemm2(const bf16* __restrict__ Ah_g, const bf16* __restrict__ Al_g,
      const bf16* __restrict__ Bh_g, const bf16* __restrict__ Bl_g,
      float* __restrict__ Cf, bf16* __restrict__ Ch_p, bf16* __restrict__ Cl_p,
      int K, int lda, int ldb, int ldc,
      long long sA, long long sB, long long sC)
{
    extern __shared__ char smem[];
    gemm_body<BKN,OSPLIT,PROJ,AVM>(Ah_g, Al_g, Bh_g, Bl_g, Cf, Ch_p, Cl_p,
                                   K, lda, ldb, ldc, sA, sB, sC, blockIdx.z, smem);
}

// merged tri-projection: z 0,1 = Q/K (bf16 3-pass); z 2 = V (fp16 2-pass)
__global__ void __launch_bounds__(256, 2)
proj_all_kernel(const bf16* __restrict__ xh, const bf16* __restrict__ xl)
{
    extern __shared__ char smem[];
    const int z = blockIdx.z;
    if (z < 2) {
        gemm_body<1,1,1,0>(xh, xl, nullptr, nullptr, nullptr, nullptr, nullptr,
                           DIM, DIM, DIM, DIM, 0, 0, 0, z, smem);
    } else {
        gemm_body<1,2,2,1>(nullptr, nullptr, nullptr, nullptr, nullptr, nullptr, nullptr,
                           DIM, DIM, DIM, DIM, 0, 0, 0, z, smem);
    }
}

// ---------------- kernel: softmax phase 2 (fp16 scores + tile maxes) ----------
__global__ void softmax2_kernel()
{
    const long long lin = (long long)blockIdx.y * SEQ + blockIdx.x;
    const long long idx = (long long)BQ * SEQ - 1 - lin;   // reverse order (L2-hot)
    const int z    = (int)(idx >> 10);
    const int rrow = (int)(idx & (SEQ - 1));
    const __half* src = g_sp + ((size_t)z * SEQ + rrow) * SEQ;
    __half*       dst = g_af + ((size_t)z * SEQ + rrow) * SEQ;
    const int tid = threadIdx.x;
    const int warp = tid >> 5, lane = tid & 31;

    // tile maxes (broadcast loads; rrow uniform per block)
    const float* st = g_stats + (size_t)z * 8 * SEQ + rrow;
    float mt_[8];
    float gmax = -1e30f;
    #pragma unroll
    for (int t = 0; t < 8; t++) { mt_[t] = st[(size_t)t * SEQ]; gmax = fmaxf(gmax, mt_[t]); }
    const float dm = mt_[tid >> 5] - gmax;   // this thread's 4 cols share one tile

    __half2 v01 = *(const __half2*)&src[tid * 4];
    __half2 v23 = *(const __half2*)&src[tid * 4 + 2];
    float2 f01 = __half22float2(v01), f23 = __half22float2(v23);
    float e0 = __expf(f01.x + dm), e1 = __expf(f01.y + dm);
    float e2 = __expf(f23.x + dm), e3 = __expf(f23.y + dm);

    float sum = e0 + e1 + e2 + e3;
    __shared__ float redS[8];
    #pragma unroll
    for (int o = 16; o > 0; o >>= 1) sum += __shfl_xor_sync(0xFFFFFFFFu, sum, o);
    if (lane == 0) redS[warp] = sum;
    __syncthreads();
    sum = redS[0]+redS[1]+redS[2]+redS[3]+redS[4]+redS[5]+redS[6]+redS[7];

    const float inv = 1.0f / sum;
    *(__half2*)&dst[tid * 4]     = __floats2half2_rn(e0 * inv, e1 * inv);
    *(__half2*)&dst[tid * 4 + 2] = __floats2half2_rn(e2 * inv, e3 * inv);
}

// ---------------------------------------------------------------------------
extern "C" void kernel_launch(void* const* d_in, const int* in_sizes, int n_in,
                              void* d_out, int out_size)
{
    const int*   inp   = (const int*)  d_in[0];
    const float* wemb  = (const float*)d_in[1];
    const float* pemb  = (const float*)d_in[2];
    const float* gamma = (const float*)d_in[3];
    const float* beta  = (const float*)d_in[4];
    const float* Wk    = (const float*)d_in[5];
    const float* Wq    = (const float*)d_in[6];
    const float* Wv    = (const float*)d_in[7];
    float* out = (float*)d_out;

    bf16 *xh,*xl,*qh,*ql,*kh,*kl;
    __half *vf,*af;
    cudaGetSymbolAddress((void**)&xh, g_xh); cudaGetSymbolAddress((void**)&xl, g_xl);
    cudaGetSymbolAddress((void**)&qh, g_qh); cudaGetSymbolAddress((void**)&ql, g_ql);
    cudaGetSymbolAddress((void**)&kh, g_kh); cudaGetSymbolAddress((void**)&kl, g_kl);
    cudaGetSymbolAddress((void**)&vf, g_vf);
    cudaGetSymbolAddress((void**)&af, g_af);

    const int SMEMSZ = 3 * 32768;  // 98304 B -> 2 CTAs/SM
    cudaFuncSetAttribute(proj_all_kernel, cudaFuncAttributeMaxDynamicSharedMemorySize, SMEMSZ);
    cudaFuncSetAttribute(gemm2<0,3,0,0>, cudaFuncAttributeMaxDynamicSharedMemorySize, SMEMSZ);
    cudaFuncSetAttribute(gemm2<1,0,0,2>, cudaFuncAttributeMaxDynamicSharedMemorySize, SMEMSZ);

    // 1) embedding + layernorm + weight split in ONE launch
    const int splitBlocks = 3 * DIM * DIM / 512;   // 1536
    embed_ln_split_kernel<<<NTOK + splitBlocks, 128>>>(inp, wemb, pemb, gamma, beta,
                                                       Wq, Wk, Wv);

    // 2) ALL projections in one launch (z: 0=Q, 1=K bf16 3-pass; 2=V fp16 2-pass)
    dim3 gproj(DIM/128, NTOK/128, 3);
    proj_all_kernel<<<gproj, 256, SMEMSZ>>>(xh, xl);

    // 3) scores = Q @ K^T — fp16 shifted store + per-tile row maxes
    dim3 gsc(SEQ/128, SEQ/128, BQ);
    gemm2<0,3,0,0><<<gsc, 256, SMEMSZ>>>(qh, ql, kh, kl, nullptr, nullptr, nullptr,
                                         DIM, DIM, DIM, SEQ,
                                         (long long)SEQ*DIM, (long long)SEQ*DIM,
                                         (long long)SEQ*SEQ);

    // 4) softmax phase 2: fp16 scores -> attn fp16
    softmax2_kernel<<<dim3(SEQ, BQ), 256>>>();

    // 5) out = attn(fp16) @ V(fp16 single), 1 MMA pass
    dim3 gav(DIM/128, SEQ/128, BQ);
    gemm2<1,0,0,2><<<gav, 256, SMEMSZ>>>((const bf16*)af, nullptr, (const bf16*)vf, nullptr,
                                         out, nullptr, nullptr,
                                         SEQ, SEQ, DIM, DIM,
                                         (long long)SEQ*SEQ, (long long)SEQ*DIM,
                                         (long long)SEQ*DIM);
}